// round 15
// baseline (speedup 1.0000x reference)
#include <cuda_runtime.h>
#include <cuda_bf16.h>
#include <cuda_fp16.h>
#include <math.h>

#define B 8
#define S 8192
#define D 64
#define H 8
#define NB 128
#define BSZ 64
#define CHUNKS 1024

typedef unsigned long long ull;

// ---------- packed f32x2 helpers (sm_100+) ----------
__device__ __forceinline__ ull fma2(ull a, ull b, ull c) {
    ull d; asm("fma.rn.f32x2 %0, %1, %2, %3;" : "=l"(d) : "l"(a), "l"(b), "l"(c)); return d;
}
__device__ __forceinline__ ull pack2(float x, float y) {
    ull r; asm("mov.b64 %0, {%1,%2};" : "=l"(r) : "f"(x), "f"(y)); return r;
}
__device__ __forceinline__ void unpack2(float& x, float& y, ull r) {
    asm("mov.b64 {%0,%1}, %2;" : "=f"(x), "=f"(y) : "l"(r));
}

__device__ __forceinline__ unsigned smem_u32(const void* p) {
    unsigned a; asm("{ .reg .u64 t; cvta.to.shared.u64 t, %1; cvt.u32.u64 %0, t; }" : "=r"(a) : "l"(p));
    return a;
}

// ---------- warp MMA helpers (sm_80+ baseline) ----------
__device__ __forceinline__ void ldsm4(unsigned& r0, unsigned& r1, unsigned& r2, unsigned& r3,
                                      unsigned addr) {
    asm volatile("ldmatrix.sync.aligned.m8n8.x4.shared.b16 {%0,%1,%2,%3}, [%4];"
                 : "=r"(r0), "=r"(r1), "=r"(r2), "=r"(r3) : "r"(addr));
}
__device__ __forceinline__ void ldsm4t(unsigned& r0, unsigned& r1, unsigned& r2, unsigned& r3,
                                       unsigned addr) {
    asm volatile("ldmatrix.sync.aligned.m8n8.x4.trans.shared.b16 {%0,%1,%2,%3}, [%4];"
                 : "=r"(r0), "=r"(r1), "=r"(r2), "=r"(r3) : "r"(addr));
}
__device__ __forceinline__ void mma_fp16(float* c, unsigned a0, unsigned a1, unsigned a2, unsigned a3,
                                         unsigned b0, unsigned b1) {
    asm volatile("mma.sync.aligned.m16n8k16.row.col.f32.f16.f16.f32 "
                 "{%0,%1,%2,%3}, {%4,%5,%6,%7}, {%8,%9}, {%0,%1,%2,%3};"
                 : "+f"(c[0]), "+f"(c[1]), "+f"(c[2]), "+f"(c[3])
                 : "r"(a0), "r"(a1), "r"(a2), "r"(a3), "r"(b0), "r"(b1));
}
__device__ __forceinline__ unsigned hpair(__half a, __half b) {
    __half2 p; p.x = a; p.y = b;
    return *(unsigned*)&p;
}

// -------- device scratch --------
__device__ unsigned char  g_bucket[B * H * S];
__device__ unsigned short g_st[B * H * S];
__device__ float          g_logits[B * H * S];
__device__ __half         g_o[(size_t)B * H * S * D];     // fp16 O
__device__ __half         g_qk16[(size_t)B * S * D];      // fp16 qk
__device__ __half         g_v16[(size_t)B * S * D];       // fp16 v
__device__ float          g_srn[B * S];                   // per-token 0.125/||k||

// ============================================================
// K0: prep — fp16 copies of qk/v + per-token key scale.
// ============================================================
__global__ __launch_bounds__(256) void prep_kernel(const float* __restrict__ qk,
                                                   const float* __restrict__ vin)
{
    int idx = blockIdx.x * 256 + threadIdx.x;
    int tok = idx >> 4;
    int q4 = idx & 15;

    float4 f4 = ((const float4*)qk)[(size_t)tok * 16 + q4];
    float ss = f4.x*f4.x + f4.y*f4.y + f4.z*f4.z + f4.w*f4.w;
    ss += __shfl_xor_sync(0xffffffffu, ss, 1);
    ss += __shfl_xor_sync(0xffffffffu, ss, 2);
    ss += __shfl_xor_sync(0xffffffffu, ss, 4);
    ss += __shfl_xor_sync(0xffffffffu, ss, 8);
    if (q4 == 0)
        g_srn[tok] = 0.125f / fmaxf(sqrtf(ss), 1e-12f);

    uint2 kp;
    kp.x = hpair(__float2half_rn(f4.x), __float2half_rn(f4.y));
    kp.y = hpair(__float2half_rn(f4.z), __float2half_rn(f4.w));
    *(uint2*)(g_qk16 + (size_t)tok * D + q4 * 4) = kp;

    float4 v4 = ((const float4*)vin)[(size_t)tok * 16 + q4];
    uint2 vp;
    vp.x = hpair(__float2half_rn(v4.x), __float2half_rn(v4.y));
    vp.y = hpair(__float2half_rn(v4.z), __float2half_rn(v4.w));
    *(uint2*)(g_v16 + (size_t)tok * D + q4 * 4) = vp;
}

// ============================================================
// K1: LSH hashing (fp32).  2 tokens/thread, two half-passes.
// ============================================================
#define HQ_STRIDE 132
#define HASH_SMEM_B 58368

__global__ __launch_bounds__(128) void hash_kernel(const float* __restrict__ qk,
                                                   const float* __restrict__ rot)
{
    extern __shared__ float hsm[];
    float* srot = hsm;                    // [f*64 + i]
    float* sqT  = hsm + 4096;             // [f*132 + tok]
    float* sPv  = hsm + 12544;            // [g*128 + tok]
    float* sNv  = hsm + 13056;
    int*   sPi  = (int*)(hsm + 13568);
    int*   sNi  = (int*)(hsm + 14080);

    int b = blockIdx.z, h = blockIdx.y, tile = blockIdx.x;
    int tid = threadIdx.x;

    for (int idx = tid; idx < 64 * 64; idx += 128) {
        int f = idx >> 6, i = idx & 63;
        srot[idx] = rot[(size_t)f * (H * 64) + h * 64 + i];
    }
    int t0 = tile * 128;
    {
        const float4* qr = (const float4*)(qk + ((size_t)b * S + t0 + tid) * D);
#pragma unroll
        for (int i = 0; i < 16; i++) {
            float4 f4 = qr[i];
            sqT[(4*i + 0) * HQ_STRIDE + tid] = f4.x;
            sqT[(4*i + 1) * HQ_STRIDE + tid] = f4.y;
            sqT[(4*i + 2) * HQ_STRIDE + tid] = f4.z;
            sqT[(4*i + 3) * HQ_STRIDE + tid] = f4.w;
        }
    }
    __syncthreads();

    int g = tid >> 5, lane = tid & 31;
    const float* rbase = srot + g * 16;

    for (int hp = 0; hp < 2; hp++) {
        int tok0 = hp * 64 + lane * 2;
        ull acc[16];
#pragma unroll
        for (int i = 0; i < 16; i++) acc[i] = 0ull;

        const float* qbase = sqT + tok0;
        for (int f = 0; f < 64; f++) {
            const ulonglong2* rp = (const ulonglong2*)(rbase + f * 64);
            ulonglong2 u0 = rp[0], u1 = rp[1];
            const ulonglong2* rp2 = (const ulonglong2*)(rbase + f * 64 + 8);
            ulonglong2 u2 = rp2[0], u3 = rp2[1];
            float2 q2 = *(const float2*)(qbase + f * HQ_STRIDE);
            ull rr[8] = { u0.x, u0.y, u1.x, u1.y, u2.x, u2.y, u3.x, u3.y };
            ull qq0 = pack2(q2.x, q2.x);
            ull qq1 = pack2(q2.y, q2.y);
#pragma unroll
            for (int i = 0; i < 8; i++) {
                acc[i]     = fma2(qq0, rr[i], acc[i]);
                acc[8 + i] = fma2(qq1, rr[i], acc[8 + i]);
            }
        }

#pragma unroll
        for (int tt = 0; tt < 2; tt++) {
            float bestP = -INFINITY, bestN = -INFINITY;
            int ip = 0, inn = 0;
#pragma unroll
            for (int i = 0; i < 8; i++) {
                float lo, hi; unpack2(lo, hi, acc[tt*8 + i]);
                int col = g * 16 + 2 * i;
                if (lo > bestP)  { bestP = lo;  ip  = col;     }
                if (hi > bestP)  { bestP = hi;  ip  = col + 1; }
                if (-lo > bestN) { bestN = -lo; inn = col;     }
                if (-hi > bestN) { bestN = -hi; inn = col + 1; }
            }
            int tok = tok0 + tt;
            sPv[g * 128 + tok] = bestP; sPi[g * 128 + tok] = ip;
            sNv[g * 128 + tok] = bestN; sNi[g * 128 + tok] = inn;
        }
    }
    __syncthreads();

    {
        float bestP = sPv[tid], bestN = sNv[tid];
        int ip = sPi[tid], inn = sNi[tid];
#pragma unroll
        for (int gg = 1; gg < 4; gg++) {
            float v = sPv[gg * 128 + tid];
            if (v > bestP) { bestP = v; ip = sPi[gg * 128 + tid]; }
            float w = sNv[gg * 128 + tid];
            if (w > bestN) { bestN = w; inn = sNi[gg * 128 + tid]; }
        }
        int bucket = (bestP >= bestN) ? ip : (64 + inn);
        g_bucket[((size_t)b * H + h) * S + t0 + tid] = (unsigned char)bucket;
    }
}

// ============================================================
// K2: stable counting sort, 256 threads, 2 segments per bucket.
// ============================================================
__global__ __launch_bounds__(256) void sort_kernel()
{
    int bh = blockIdx.x;
    __shared__ unsigned char sb[S];
    __shared__ int histA[NB];
    __shared__ int histB[NB];
    __shared__ int base[NB];
    int tid = threadIdx.x;

    if (tid < NB) { histA[tid] = 0; histB[tid] = 0; }
    __syncthreads();

    const uchar4* src = (const uchar4*)(g_bucket + (size_t)bh * S);
    for (int i = tid; i < S / 4; i += 256) {
        uchar4 u = src[i];
        ((uchar4*)sb)[i] = u;
        int* hist = (i < S / 8) ? histA : histB;
        atomicAdd(&hist[u.x], 1);
        atomicAdd(&hist[u.y], 1);
        atomicAdd(&hist[u.z], 1);
        atomicAdd(&hist[u.w], 1);
    }
    __syncthreads();

    if (tid == 0) {
        int s = 0;
        for (int k = 0; k < NB; k++) { base[k] = s; s += histA[k] + histB[k]; }
    }
    __syncthreads();

    int myb = tid & 127;
    int seg = tid >> 7;
    int cnt = base[myb] + (seg ? histA[myb] : 0);
    int i0 = seg ? S / 2 : 0;
    int i1 = i0 + S / 2;
    unsigned short* dst = g_st + (size_t)bh * S;
    for (int i = i0; i < i1; i += 4) {
        uchar4 u = *(const uchar4*)(sb + i);
        if (u.x == myb) dst[cnt++] = (unsigned short)(i);
        if (u.y == myb) dst[cnt++] = (unsigned short)(i + 1);
        if (u.z == myb) dst[cnt++] = (unsigned short)(i + 2);
        if (u.w == myb) dst[cnt++] = (unsigned short)(i + 3);
    }
}

// ============================================================
// K3: mma.sync attention v8 — half-split MMA1 + fused
// epilogue/MMA2 per key-half.  cS[32] + transient A-fragments
// cut peak registers (-> higher occupancy).  Accumulation order
// per output element identical to v7 -> bit-identical results.
//
// smem: skid 512 | srn 512 | KQ 18432 | V 18432 = 37888
// ============================================================
#define SM_SKID 0
#define SM_SRN  512
#define SM_KQ   1024
#define SM_VH   19456
#define ATTN_SMEM_B 37888
#define KQ_STRIDE 144     // bytes (72 fp16)

__global__ __launch_bounds__(128) void attn_kernel()
{
    extern __shared__ char smem[];
    unsigned sbase = smem_u32(smem);
    int tid = threadIdx.x;
    int b = blockIdx.y, c = blockIdx.x, h = c >> 7;
    int* skid = (int*)(smem + SM_SKID);
    float* srn_s = (float*)(smem + SM_SRN);

    int lane = tid & 31, warp = tid >> 5;

    // ---------------- staging: coalesced fp16 gather ----------------
    {
        int slot = tid;
        int kc = (slot < 64) ? c : ((c + CHUNKS - 1) & (CHUNKS - 1));
        const unsigned short* ST = g_st + (size_t)b * (H * S);
        int kt = ST[kc * BSZ + (slot & 63)];
        skid[slot] = kt;
        srn_s[slot] = g_srn[b * S + kt];

        int sub = lane >> 3;
        int q8 = lane & 7;
        const size_t brow = (size_t)b * S;

#pragma unroll
        for (int it = 0; it < 8; it++) {
            int s2 = warp * 32 + it * 4 + sub;
            int tok = __shfl_sync(0xffffffffu, kt, it * 4 + sub);
            uint4 kk = ((const uint4*)(g_qk16 + (brow + tok) * D))[q8];
            *(uint4*)(smem + SM_KQ + s2 * KQ_STRIDE + q8 * 16) = kk;
            uint4 vv = ((const uint4*)(g_v16 + (brow + tok) * D))[q8];
            *(uint4*)(smem + SM_VH + s2 * KQ_STRIDE + q8 * 16) = vv;
        }
    }
    __syncthreads();

    int wr = warp * 16;
    int g = lane >> 2, tg = lane & 3;

    unsigned aRowOff = (unsigned)((wr + (lane & 15)) * KQ_STRIDE + (lane >> 4) * 16);
    unsigned bn  = (lane & 7) + ((lane >> 4) << 3);
    unsigned bkh = (lane >> 3) & 1;
    unsigned vRow = lane & 15, vColHalf = lane >> 4;

    int r1 = wr + g, r2 = r1 + 8;
    int tok1 = skid[r1], tok2 = skid[r2];
    float l1 = 0.f, l2 = 0.f;

    float oacc[32];
#pragma unroll
    for (int i = 0; i < 32; i++) oacc[i] = 0.f;

#pragma unroll
    for (int hf = 0; hf < 2; hf++) {
        // -------- MMA1 half: keys hf*64 .. hf*64+63 --------
        float cS[32];
#pragma unroll
        for (int i = 0; i < 32; i++) cS[i] = 0.f;

#pragma unroll
        for (int ks = 0; ks < 4; ks++) {
            unsigned aaddr = sbase + SM_KQ + aRowOff + ks * 32;
            unsigned aH0, aH1, aH2, aH3;
            ldsm4(aH0, aH1, aH2, aH3, aaddr);
#pragma unroll
            for (int jp4 = 0; jp4 < 4; jp4++) {
                int jp = hf * 4 + jp4;
                unsigned baddr = sbase + SM_KQ + (jp * 16 + bn) * KQ_STRIDE + bkh * 16 + ks * 32;
                unsigned bH0, bH1, bH2, bH3;
                ldsm4(bH0, bH1, bH2, bH3, baddr);
                mma_fp16(cS + (2*jp4) * 4,     aH0, aH1, aH2, aH3, bH0, bH1);
                mma_fp16(cS + (2*jp4 + 1) * 4, aH0, aH1, aH2, aH3, bH2, bH3);
            }
        }

        // -------- fused epilogue + MMA2 for this half --------
#pragma unroll
        for (int m = 0; m < 4; m++) {
            int jE = hf * 8 + 2 * m;           // even j (global)
            int jcE = jE * 8 + tg * 2;
            int jcO = jcE + 8;
            // even j -> a0, a1
            float p00, p01, p10, p11;
            {
                int kid0 = skid[jcE], kid1 = skid[jcE + 1];
                float sc0 = srn_s[jcE], sc1 = srn_s[jcE + 1];
                p00 = (kid0 == tok1) ? 0.f : __expf(cS[(2*m)*4 + 0] * sc0);
                p01 = (kid1 == tok1) ? 0.f : __expf(cS[(2*m)*4 + 1] * sc1);
                p10 = (kid0 == tok2) ? 0.f : __expf(cS[(2*m)*4 + 2] * sc0);
                p11 = (kid1 == tok2) ? 0.f : __expf(cS[(2*m)*4 + 3] * sc1);
                l1 += p00 + p01;
                l2 += p10 + p11;
            }
            __half h00 = __float2half_rn(p00), h01 = __float2half_rn(p01);
            __half h10 = __float2half_rn(p10), h11 = __float2half_rn(p11);
            unsigned aHi0 = hpair(h00, h01);
            unsigned aHi1 = hpair(h10, h11);
            unsigned aLo0 = hpair(__float2half_rn(p00 - __half2float(h00)),
                                  __float2half_rn(p01 - __half2float(h01)));
            unsigned aLo1 = hpair(__float2half_rn(p10 - __half2float(h10)),
                                  __float2half_rn(p11 - __half2float(h11)));
            // odd j -> a2, a3
            {
                int kid0 = skid[jcO], kid1 = skid[jcO + 1];
                float sc0 = srn_s[jcO], sc1 = srn_s[jcO + 1];
                p00 = (kid0 == tok1) ? 0.f : __expf(cS[(2*m+1)*4 + 0] * sc0);
                p01 = (kid1 == tok1) ? 0.f : __expf(cS[(2*m+1)*4 + 1] * sc1);
                p10 = (kid0 == tok2) ? 0.f : __expf(cS[(2*m+1)*4 + 2] * sc0);
                p11 = (kid1 == tok2) ? 0.f : __expf(cS[(2*m+1)*4 + 3] * sc1);
                l1 += p00 + p01;
                l2 += p10 + p11;
            }
            __half h20 = __float2half_rn(p00), h21 = __float2half_rn(p01);
            __half h30 = __float2half_rn(p10), h31 = __float2half_rn(p11);
            unsigned aHi2 = hpair(h20, h21);
            unsigned aHi3 = hpair(h30, h31);
            unsigned aLo2 = hpair(__float2half_rn(p00 - __half2float(h20)),
                                  __float2half_rn(p01 - __half2float(h21)));
            unsigned aLo3 = hpair(__float2half_rn(p10 - __half2float(h30)),
                                  __float2half_rn(p11 - __half2float(h31)));

            int ks2 = hf * 4 + m;
#pragma unroll
            for (int jp = 0; jp < 4; jp++) {
                unsigned baddr = sbase + SM_VH + (ks2 * 16 + vRow) * KQ_STRIDE + vColHalf * 16 + jp * 32;
                unsigned vH0, vH1, vH2, vH3;
                ldsm4t(vH0, vH1, vH2, vH3, baddr);
                float* o0 = oacc + (2*jp) * 4;
                float* o1 = oacc + (2*jp + 1) * 4;
                mma_fp16(o0, aHi0, aHi1, aHi2, aHi3, vH0, vH1);
                mma_fp16(o0, aLo0, aLo1, aLo2, aLo3, vH0, vH1);
                mma_fp16(o1, aHi0, aHi1, aHi2, aHi3, vH2, vH3);
                mma_fp16(o1, aLo0, aLo1, aLo2, aLo3, vH2, vH3);
            }
        }
    }

    // ---------------- finish: l-reduce, logits, normalize, scatter ----------------
    l1 += __shfl_xor_sync(0xffffffffu, l1, 1);
    l1 += __shfl_xor_sync(0xffffffffu, l1, 2);
    l2 += __shfl_xor_sync(0xffffffffu, l2, 1);
    l2 += __shfl_xor_sync(0xffffffffu, l2, 2);
    float linv1 = 1.f / l1, linv2 = 1.f / l2;
    if (tg == 0) {
        size_t lbase = (size_t)(b * H + h) * S;
        g_logits[lbase + tok1] = __logf(l1);
        g_logits[lbase + tok2] = __logf(l2);
    }

    __half* orow1 = g_o + (((size_t)(b * H + h) * S + tok1) * D);
    __half* orow2 = g_o + (((size_t)(b * H + h) * S + tok2) * D);
#pragma unroll
    for (int j = 0; j < 8; j++) {
        int col = j * 8 + tg * 2;
        *(unsigned*)(orow1 + col) = hpair(__float2half_rn(oacc[j*4 + 0] * linv1),
                                          __float2half_rn(oacc[j*4 + 1] * linv1));
        *(unsigned*)(orow2 + col) = hpair(__float2half_rn(oacc[j*4 + 2] * linv2),
                                          __float2half_rn(oacc[j*4 + 3] * linv2));
    }
}

// ============================================================
// K4: combine the H rounds.  Warp = 1 token, lane = half2 dim pair.
// ============================================================
__global__ __launch_bounds__(256) void combine_kernel(float* __restrict__ out)
{
    int bt = blockIdx.x * 8 + (threadIdx.x >> 5);
    int b = bt >> 13, t = bt & (S - 1);
    int d2 = threadIdx.x & 31;

    float lg[H];
    float mx = -INFINITY;
    size_t lbase = ((size_t)b * H) * S + t;
#pragma unroll
    for (int h = 0; h < H; h++) {
        lg[h] = g_logits[lbase + (size_t)h * S];
        mx = fmaxf(mx, lg[h]);
    }
    float sum = 0.f;
#pragma unroll
    for (int h = 0; h < H; h++) { lg[h] = __expf(lg[h] - mx); sum += lg[h]; }

    float a0 = 0.f, a1 = 0.f;
#pragma unroll
    for (int h = 0; h < H; h++) {
        __half2 v = *(const __half2*)(g_o + ((lbase + (size_t)h * S) * D) + 2 * d2);
        float2 vf = __half22float2(v);
        a0 += lg[h] * vf.x;
        a1 += lg[h] * vf.y;
    }

    float inv = 1.f / sum;
    *(float2*)(out + ((size_t)b * S + t) * D + 2 * d2) = make_float2(a0 * inv, a1 * inv);
}

// ============================================================
extern "C" void kernel_launch(void* const* d_in, const int* in_sizes, int n_in,
                              void* d_out, int out_size)
{
    const float* qk  = (const float*)d_in[0];
    const float* v   = (const float*)d_in[1];
    const float* rot = (const float*)d_in[2];
    float* out = (float*)d_out;

    cudaFuncSetAttribute(attn_kernel, cudaFuncAttributeMaxDynamicSharedMemorySize, ATTN_SMEM_B);
    cudaFuncSetAttribute(hash_kernel, cudaFuncAttributeMaxDynamicSharedMemorySize, HASH_SMEM_B);

    prep_kernel<<<B * S * 16 / 256, 256>>>(qk, v);
    hash_kernel<<<dim3(S / 128, H, B), 128, HASH_SMEM_B>>>(qk, rot);
    sort_kernel<<<B * H, 256>>>();
    attn_kernel<<<dim3(CHUNKS, B), 128, ATTN_SMEM_B>>>();
    combine_kernel<<<B * S / 8, 256>>>(out);
}